// round 12
// baseline (speedup 1.0000x reference)
#include <cuda_runtime.h>
#include <cuda_bf16.h>
#include <math.h>
#include <stdint.h>

// ---------------- problem constants ----------------
#define NB 4
#define NL 2048
#define ND 1024
#define NH 16
#define NDH 64
#define NW 128
#define NCS 32
#define NNC 128          // total compressed keys (64 cache + 64 block)
#define NNQ 64           // L / CS
#define NCACHE 2048
#define NWINROWS (NW + NL)   // 2176

typedef unsigned long long ull;

// ---------------- scratch buffers (device globals; no mallocs allowed) ----------------
__device__ float g_q[NB*NL*ND];
__device__ float g_kbp[NB*NL*ND];
__device__ float g_vbp[NB*NL*ND];
__device__ float g_sh[NB*NL*NH];
__device__ float g_shc[NB*NCACHE*NH];
__device__ float g_sch[NB*NH*NNQ*NCS];
__device__ float g_schc[NB*NH*NNQ*NCS];
__device__ float g_hcm[NB*NNQ*ND];
__device__ float g_hcmk[NB*NNQ*ND];
__device__ float g_hcmv[NB*NNQ*ND];
__device__ float g_kcomp[NB*NNC*ND];
__device__ float g_vcomp[NB*NNC*ND];
__device__ float g_hwk[NB*NW*ND];
__device__ float g_hwv[NB*NW*ND];
__device__ float g_kwin[NB*NWINROWS*ND];
__device__ float g_vwin[NB*NWINROWS*ND];
__device__ float g_post[NW*ND];
__device__ float g_posc[NNC*ND];

// bf16 hi/lo split buffers (per-chain to avoid false dependencies)
__device__ __nv_bfloat16 g_ahi[NB*NL*ND];
__device__ __nv_bfloat16 g_alo[NB*NL*ND];
__device__ __nv_bfloat16 g_xhi[256*ND],  g_xlo[256*ND];    // hcm (s1)
__device__ __nv_bfloat16 g_yhi[512*ND],  g_ylo[512*ND];    // hw (s2)
__device__ __nv_bfloat16 g_phi[NW*ND],   g_plo[NW*ND];     // poswin (s2)
__device__ __nv_bfloat16 g_ehi[NNC*ND],  g_elo[NNC*ND];    // key_pe (s2)
__device__ __nv_bfloat16 g_wqkvh[3*ND*ND], g_wqkvl[3*ND*ND];   // rows: q(scaled)|k|v
__device__ __nv_bfloat16 g_woh[ND*ND], g_wol[ND*ND];
__device__ __nv_bfloat16 g_wrh[ND*ND], g_wrl[ND*ND];
__device__ __nv_bfloat16 g_wrch[ND*ND], g_wrcl[ND*ND];

// ================= low-level helpers =================
__device__ __forceinline__ uint32_t smem_u32(const void* p) {
    uint32_t a;
    asm("{ .reg .u64 t; cvta.to.shared.u64 t, %1; cvt.u32.u64 %0, t; }" : "=r"(a) : "l"(p));
    return a;
}
__device__ __forceinline__ void ldm_x4(uint32_t& r0, uint32_t& r1, uint32_t& r2, uint32_t& r3,
                                       uint32_t addr) {
    asm volatile("ldmatrix.sync.aligned.m8n8.x4.shared.b16 {%0,%1,%2,%3}, [%4];"
                 : "=r"(r0), "=r"(r1), "=r"(r2), "=r"(r3) : "r"(addr));
}
__device__ __forceinline__ void mma_bf16(float* c, const uint32_t* a, uint32_t b0, uint32_t b1) {
    asm volatile("mma.sync.aligned.m16n8k16.row.col.f32.bf16.bf16.f32 "
                 "{%0,%1,%2,%3}, {%4,%5,%6,%7}, {%8,%9}, {%0,%1,%2,%3};"
                 : "+f"(c[0]), "+f"(c[1]), "+f"(c[2]), "+f"(c[3])
                 : "r"(a[0]), "r"(a[1]), "r"(a[2]), "r"(a[3]), "r"(b0), "r"(b1));
}
#define CP16(dst, src) \
    asm volatile("cp.async.cg.shared.global [%0], [%1], 16;" :: "r"(dst), "l"(src))
#define CP_COMMIT() asm volatile("cp.async.commit_group;" ::: "memory")
#define CP_WAIT1()  asm volatile("cp.async.wait_group 1;" ::: "memory")

// packed fp32x2 math (SASS FFMA2 — PTX-only)
__device__ __forceinline__ void fma2(ull& d, ull a, ull b) {
    asm("fma.rn.f32x2 %0, %1, %2, %0;" : "+l"(d) : "l"(a), "l"(b));
}
__device__ __forceinline__ ull add2(ull a, ull b) {
    ull r; asm("add.rn.f32x2 %0, %1, %2;" : "=l"(r) : "l"(a), "l"(b)); return r;
}
__device__ __forceinline__ ull pack2(float x) {
    ull r; asm("mov.b64 %0, {%1, %1};" : "=l"(r) : "f"(x)); return r;
}
__device__ __forceinline__ float fold2(ull v) {
    float lo, hi; asm("mov.b64 {%0, %1}, %2;" : "=f"(lo), "=f"(hi) : "l"(v)); return lo + hi;
}
__device__ __forceinline__ float2 unpack2(ull v) {
    float2 r; asm("mov.b64 {%0, %1}, %2;" : "=f"(r.x), "=f"(r.y) : "l"(v)); return r;
}

// ================= tensor-core GEMM (double-buffered, 2 CTAs/SM) =================
#define TSTR 40
#define TILE_B (128 * TSTR * 2)
#define BUF_B  (4 * TILE_B)
#define TG_SMEM_TOTAL (2 * BUF_B)      // 81920 -> 2 CTAs/SM

__global__ void __launch_bounds__(256)
tgemm_kernel(const __nv_bfloat16* __restrict__ Ahi, const __nv_bfloat16* __restrict__ Alo,
             const __nv_bfloat16* __restrict__ Bhi, const __nv_bfloat16* __restrict__ Blo,
             const float* __restrict__ bias,
             float* __restrict__ C0, float* __restrict__ C1, float* __restrict__ C2,
             int M, int N, int K)
{
    extern __shared__ char smc[];
    const uint32_t sbase = smem_u32(smc);
    const int tid = threadIdx.x;
    const int wid = tid >> 5, lane = tid & 31;
    const int row0 = blockIdx.y << 7;
    const int col0 = blockIdx.x << 7;
    const int wm = wid >> 1;
    const int wn = wid & 1;

    const __nv_bfloat16* srcs[4] = {Ahi, Alo, Bhi, Blo};
    const int nch = K >> 5;

    {
        #pragma unroll
        for (int it = 0; it < 8; it++) {
            int id = tid + it * 256;
            int t = id >> 9;
            int j = id & 511;
            int r = j >> 2;
            int ch = j & 3;
            long grow = (t < 2) ? (long)(row0 + r) : (long)(col0 + r);
            CP16(sbase + t * TILE_B + r * (TSTR * 2) + ch * 16,
                 srcs[t] + grow * K + ch * 8);
        }
        CP_COMMIT();
    }

    float acc[2][8][4];
    #pragma unroll
    for (int mt = 0; mt < 2; mt++)
        #pragma unroll
        for (int nt = 0; nt < 8; nt++)
            #pragma unroll
            for (int f = 0; f < 4; f++) acc[mt][nt][f] = 0.f;

    const int lrow = lane & 15;
    const int lcol = (lane >> 4) * 16;

    for (int kc = 0; kc < nch; kc++) {
        const uint32_t buf = sbase + (kc & 1) * BUF_B;
        if (kc + 1 < nch) {
            const long kb = (long)(kc + 1) << 5;
            const uint32_t nbuf = sbase + ((kc + 1) & 1) * BUF_B;
            #pragma unroll
            for (int it = 0; it < 8; it++) {
                int id = tid + it * 256;
                int t = id >> 9;
                int j = id & 511;
                int r = j >> 2;
                int ch = j & 3;
                long grow = (t < 2) ? (long)(row0 + r) : (long)(col0 + r);
                CP16(nbuf + t * TILE_B + r * (TSTR * 2) + ch * 16,
                     srcs[t] + grow * K + kb + ch * 8);
            }
        }
        CP_COMMIT();
        CP_WAIT1();
        __syncthreads();

        const uint32_t aBase = buf + (wm * 32 + lrow) * (TSTR * 2) + lcol;
        const uint32_t bBase = buf + 2 * TILE_B + (wn * 64 + lrow) * (TSTR * 2) + lcol;

        #pragma unroll
        for (int kk = 0; kk < 2; kk++) {
            const uint32_t ko = kk * 32;
            uint32_t ah[2][4], al[2][4];
            #pragma unroll
            for (int mt = 0; mt < 2; mt++) {
                ldm_x4(ah[mt][0], ah[mt][1], ah[mt][2], ah[mt][3],
                       aBase + mt * 16 * (TSTR * 2) + ko);
                ldm_x4(al[mt][0], al[mt][1], al[mt][2], al[mt][3],
                       aBase + TILE_B + mt * 16 * (TSTR * 2) + ko);
            }
            #pragma unroll
            for (int np = 0; np < 4; np++) {
                uint32_t bh0, bh1, bh2, bh3, bl0, bl1, bl2, bl3;
                ldm_x4(bh0, bh1, bh2, bh3, bBase + np * 16 * (TSTR * 2) + ko);
                ldm_x4(bl0, bl1, bl2, bl3, bBase + TILE_B + np * 16 * (TSTR * 2) + ko);
                #pragma unroll
                for (int mt = 0; mt < 2; mt++) {
                    mma_bf16(acc[mt][np * 2],     ah[mt], bh0, bh2);
                    mma_bf16(acc[mt][np * 2 + 1], ah[mt], bh1, bh3);
                    mma_bf16(acc[mt][np * 2],     al[mt], bh0, bh2);
                    mma_bf16(acc[mt][np * 2 + 1], al[mt], bh1, bh3);
                    mma_bf16(acc[mt][np * 2],     ah[mt], bl0, bl2);
                    mma_bf16(acc[mt][np * 2 + 1], ah[mt], bl1, bl3);
                }
            }
        }
        __syncthreads();
    }

    float* Cs[3] = {C0, C1, C2};
    const int g = lane >> 2, tig = lane & 3;
    #pragma unroll
    for (int mt = 0; mt < 2; mt++) {
        const long r0g = row0 + wm * 32 + mt * 16 + g;
        #pragma unroll
        for (int nt = 0; nt < 8; nt++) {
            const int cN = col0 + wn * 64 + nt * 8 + tig * 2;
            float* Cp = Cs[cN >> 10];
            const int cc = cN & 1023;
            float b0 = 0.f, b1 = 0.f;
            if (bias) { b0 = bias[cN]; b1 = bias[cN + 1]; }
            float2 o0 = make_float2(acc[mt][nt][0] + b0, acc[mt][nt][1] + b1);
            float2 o1 = make_float2(acc[mt][nt][2] + b0, acc[mt][nt][3] + b1);
            *reinterpret_cast<float2*>(Cp + r0g * 1024 + cc)       = o0;
            *reinterpret_cast<float2*>(Cp + (r0g + 8) * 1024 + cc) = o1;
        }
    }
}

// ================= fp32 -> bf16 hi/lo split (row remap supported) =================
__global__ void split_kernel(const float* __restrict__ in, __nv_bfloat16* __restrict__ hi,
                             __nv_bfloat16* __restrict__ lo, int rpb, long bstride, long off)
{
    const int r = blockIdx.x;
    const long phys = (long)(r / rpb) * bstride + off + (r % rpb);
    const int c = threadIdx.x * 4;
    float4 v = *reinterpret_cast<const float4*>(in + phys * ND + c);
    __nv_bfloat16 h0 = __float2bfloat16(v.x), h1 = __float2bfloat16(v.y);
    __nv_bfloat16 h2 = __float2bfloat16(v.z), h3 = __float2bfloat16(v.w);
    __nv_bfloat16 l0 = __float2bfloat16(v.x - __bfloat162float(h0));
    __nv_bfloat16 l1 = __float2bfloat16(v.y - __bfloat162float(h1));
    __nv_bfloat16 l2 = __float2bfloat16(v.z - __bfloat162float(h2));
    __nv_bfloat16 l3 = __float2bfloat16(v.w - __bfloat162float(h3));
    __nv_bfloat162 hp0(h0, h1), hp1(h2, h3), lp0(l0, l1), lp1(l2, l3);
    *reinterpret_cast<__nv_bfloat162*>(hi + (long)r * ND + c)     = hp0;
    *reinterpret_cast<__nv_bfloat162*>(hi + (long)r * ND + c + 2) = hp1;
    *reinterpret_cast<__nv_bfloat162*>(lo + (long)r * ND + c)     = lp0;
    *reinterpret_cast<__nv_bfloat162*>(lo + (long)r * ND + c + 2) = lp1;
}

// ================= weight transpose + split (with scale): W[K,N] -> [N,K] =================
__global__ void wsplit_kernel(const float* __restrict__ W, __nv_bfloat16* __restrict__ hiT,
                              __nv_bfloat16* __restrict__ loT, float scale)
{
    __shared__ float t[32][33];
    const int tx = threadIdx.x & 31, ty = threadIdx.x >> 5;
    const int k0 = blockIdx.y * 32, n0 = blockIdx.x * 32;
    #pragma unroll
    for (int i = 0; i < 32; i += 8)
        t[ty + i][tx] = W[(long)(k0 + ty + i) * ND + n0 + tx];
    __syncthreads();
    #pragma unroll
    for (int i = 0; i < 32; i += 8) {
        float v = t[tx][ty + i] * scale;
        __nv_bfloat16 h = __float2bfloat16(v);
        __nv_bfloat16 l = __float2bfloat16(v - __bfloat162float(h));
        hiT[(long)(n0 + ty + i) * ND + k0 + tx] = h;
        loT[(long)(n0 + ty + i) * ND + k0 + tx] = l;
    }
}

// ================= N=16 GEMV, batched over two inputs =================
__global__ void gemv16x2_kernel(const float* __restrict__ x1, const float* __restrict__ x2,
                                const float* __restrict__ Wd, const float* __restrict__ bd,
                                float* __restrict__ out1, float* __restrict__ out2,
                                int half_blocks)
{
    __shared__ float As[64][65];
    __shared__ float Ws[64][16];
    const int tid = threadIdx.x;
    const bool second = (blockIdx.x >= half_blocks);
    const float* x = second ? x2 : x1;
    float* out = second ? out2 : out1;
    const int row0 = (second ? (blockIdx.x - half_blocks) : blockIdx.x) * 64;
    const int col = tid & 15, rg = tid >> 4;
    float acc[4] = {0.f, 0.f, 0.f, 0.f};

    for (int k0 = 0; k0 < ND; k0 += 64) {
        #pragma unroll
        for (int it = 0; it < 16; it++) {
            int i = tid + it * 256;
            int r = i >> 6, c = i & 63;
            As[r][c] = x[(long)(row0 + r) * ND + k0 + c];
        }
        #pragma unroll
        for (int it = 0; it < 4; it++) {
            int i = tid + it * 256;
            int k = i >> 4, c = i & 15;
            Ws[k][c] = Wd[(long)(k0 + k) * NH + c];
        }
        __syncthreads();
        #pragma unroll 8
        for (int k = 0; k < 64; k++) {
            float w = Ws[k][col];
            #pragma unroll
            for (int j = 0; j < 4; j++) acc[j] += As[rg * 4 + j][k] * w;
        }
        __syncthreads();
    }
    #pragma unroll
    for (int j = 0; j < 4; j++)
        out[(long)(row0 + rg * 4 + j) * NH + col] = acc[j] + bd[col];
}

// ---------------- per-chunk, per-head softmax; batched over two inputs ----------------
__global__ void chunk_softmax2_kernel(const float* __restrict__ in1, const float* __restrict__ in2,
                                      float* __restrict__ out1, float* __restrict__ out2,
                                      int half_blocks)
{
    const bool second = (blockIdx.x >= half_blocks);
    const float* s_in = second ? in2 : in1;
    float* sc_out = second ? out2 : out1;
    const int bc = second ? (blockIdx.x - half_blocks) : blockIdx.x;
    const int ncx = NNQ;   // both inputs have Lx/NCS = 64 chunks
    const int b = bc / ncx, c = bc % ncx;
    const int h = threadIdx.x >> 5, s = threadIdx.x & 31;
    const int Lx = 2048;

    float v = s_in[(size_t)(b * Lx + c * NCS + s) * NH + h];
    float m = v;
    #pragma unroll
    for (int o = 16; o; o >>= 1) m = fmaxf(m, __shfl_xor_sync(0xffffffffu, m, o));
    float e = __expf(v - m);
    float sum = e;
    #pragma unroll
    for (int o = 16; o; o >>= 1) sum += __shfl_xor_sync(0xffffffffu, sum, o);
    sc_out[((size_t)(b * NH + h) * ncx + c) * NCS + s] = e / sum;
}

// ---------------- compress (plain, for hcm path) ----------------
__global__ void compress_kernel(const float* __restrict__ x, const float* __restrict__ sc,
                                float* __restrict__ out, int Lx)
{
    const int ncx = Lx / NCS;
    const int b = blockIdx.x / ncx, c = blockIdx.x % ncx;
    __shared__ float w[NH][NCS];
    const int tid = threadIdx.x;
    for (int i = tid; i < NH * NCS; i += 256) {
        int h = i >> 5, s = i & 31;
        w[h][s] = sc[((size_t)(b * NH + h) * ncx + c) * NCS + s];
    }
    __syncthreads();

    const int col = tid * 4;
    const int h = col >> 6;
    float4 acc = make_float4(0.f, 0.f, 0.f, 0.f);
    #pragma unroll 4
    for (int s = 0; s < NCS; s++) {
        float ws = w[h][s];
        float4 xv = *reinterpret_cast<const float4*>(x + (size_t)(b * Lx + c * NCS + s) * ND + col);
        acc.x += ws * xv.x; acc.y += ws * xv.y; acc.z += ws * xv.z; acc.w += ws * xv.w;
    }
    *reinterpret_cast<float4*>(out + (size_t)(b * ncx + c) * ND + col) = acc;
}

// ---------------- fused compress + LayerNorm (block K/V -> kcomp/vcomp rows 64+) ----------
__global__ void compress_ln_kernel(const float* __restrict__ xk, const float* __restrict__ xv,
                                   const float* __restrict__ sc,
                                   float* __restrict__ outk, float* __restrict__ outv,
                                   const float* __restrict__ g, const float* __restrict__ be)
{
    const int b = blockIdx.x / NNQ, c = blockIdx.x % NNQ;
    const float* x = blockIdx.y ? xv : xk;
    float* out = blockIdx.y ? outv : outk;

    __shared__ float w[NH][NCS];
    __shared__ float red[32];
    const int tid = threadIdx.x;
    for (int i = tid; i < NH * NCS; i += 256) {
        int h = i >> 5, s = i & 31;
        w[h][s] = sc[((size_t)(b * NH + h) * NNQ + c) * NCS + s];
    }
    __syncthreads();

    const int col = tid * 4;
    const int h = col >> 6;
    float4 acc = make_float4(0.f, 0.f, 0.f, 0.f);
    #pragma unroll 4
    for (int s = 0; s < NCS; s++) {
        float ws = w[h][s];
        float4 xvv = *reinterpret_cast<const float4*>(x + (size_t)(b * NL + c * NCS + s) * ND + col);
        acc.x += ws * xvv.x; acc.y += ws * xvv.y; acc.z += ws * xvv.z; acc.w += ws * xvv.w;
    }

    float s1 = acc.x + acc.y + acc.z + acc.w;
    #pragma unroll
    for (int o = 16; o; o >>= 1) s1 += __shfl_xor_sync(0xffffffffu, s1, o);
    if ((tid & 31) == 0) red[tid >> 5] = s1;
    __syncthreads();
    if (tid < 32) {
        float t = (tid < 8) ? red[tid] : 0.f;
        #pragma unroll
        for (int o = 4; o; o >>= 1) t += __shfl_xor_sync(0xffffffffu, t, o);
        if (tid == 0) red[0] = t;
    }
    __syncthreads();
    float mean = red[0] * (1.f / ND);
    __syncthreads();

    float d0 = acc.x - mean, d1 = acc.y - mean, d2 = acc.z - mean, d3 = acc.w - mean;
    float s2 = d0*d0 + d1*d1 + d2*d2 + d3*d3;
    #pragma unroll
    for (int o = 16; o; o >>= 1) s2 += __shfl_xor_sync(0xffffffffu, s2, o);
    if ((tid & 31) == 0) red[tid >> 5] = s2;
    __syncthreads();
    if (tid < 32) {
        float t = (tid < 8) ? red[tid] : 0.f;
        #pragma unroll
        for (int o = 4; o; o >>= 1) t += __shfl_xor_sync(0xffffffffu, t, o);
        if (tid == 0) red[0] = t;
    }
    __syncthreads();
    float rstd = rsqrtf(red[0] * (1.f / ND) + 1e-5f);

    const long orow = (long)b * NNC + 64 + c;
    float4 ov;
    ov.x = d0 * rstd * g[col + 0] + be[col + 0];
    ov.y = d1 * rstd * g[col + 1] + be[col + 1];
    ov.z = d2 * rstd * g[col + 2] + be[col + 2];
    ov.w = d3 * rstd * g[col + 3] + be[col + 3];
    *reinterpret_cast<float4*>(out + orow * ND + col) = ov;
}

// ---------------- dual row LayerNorm: blockIdx.y picks (in1->out1) or (in2->out2) ---------
__global__ void ln2_kernel(const float* __restrict__ in1, const float* __restrict__ in2,
                           float* __restrict__ out1, float* __restrict__ out2,
                           const float* __restrict__ g, const float* __restrict__ be,
                           int rpb, int out_bstride, int out_off)
{
    __shared__ float red[32];
    const int r = blockIdx.x;
    const int tid = threadIdx.x;
    const float* in = blockIdx.y ? in2 : in1;
    float* out = blockIdx.y ? out2 : out1;

    const float* x = in + (size_t)r * ND;
    float4 v = *reinterpret_cast<const float4*>(x + tid * 4);

    float s = v.x + v.y + v.z + v.w;
    #pragma unroll
    for (int o = 16; o; o >>= 1) s += __shfl_xor_sync(0xffffffffu, s, o);
    if ((tid & 31) == 0) red[tid >> 5] = s;
    __syncthreads();
    if (tid < 32) {
        float t = (tid < 8) ? red[tid] : 0.f;
        #pragma unroll
        for (int o = 4; o; o >>= 1) t += __shfl_xor_sync(0xffffffffu, t, o);
        if (tid == 0) red[0] = t;
    }
    __syncthreads();
    float mean = red[0] * (1.f / ND);
    __syncthreads();

    float d0 = v.x - mean, d1 = v.y - mean, d2 = v.z - mean, d3 = v.w - mean;
    float s2 = d0*d0 + d1*d1 + d2*d2 + d3*d3;
    #pragma unroll
    for (int o = 16; o; o >>= 1) s2 += __shfl_xor_sync(0xffffffffu, s2, o);
    if ((tid & 31) == 0) red[tid >> 5] = s2;
    __syncthreads();
    if (tid < 32) {
        float t = (tid < 8) ? red[tid] : 0.f;
        #pragma unroll
        for (int o = 4; o; o >>= 1) t += __shfl_xor_sync(0xffffffffu, t, o);
        if (tid == 0) red[0] = t;
    }
    __syncthreads();
    float rstd = rsqrtf(red[0] * (1.f / ND) + 1e-5f);

    const int orow = (r / rpb) * out_bstride + out_off + (r % rpb);
    const int c = tid * 4;
    float4 ov;
    ov.x = d0 * rstd * g[c + 0] + be[c + 0];
    ov.y = d1 * rstd * g[c + 1] + be[c + 1];
    ov.z = d2 * rstd * g[c + 2] + be[c + 2];
    ov.w = d3 * rstd * g[c + 3] + be[c + 3];
    *reinterpret_cast<float4*>(out + (size_t)orow * ND + c) = ov;
}

// ---------------- fused attention: rel-shift pos + scores + softmax + AV ----------------
#define ASTR 66
#define ATT_OFF_SC 2048
#define ATT_OFF_D  10240
#define ATT_OFF_KB 15360
#define ATT_OFF_RW 25920
#define ATT_OFF_RR 25984
#define ATT_SMEM_F 26048

__global__ void __launch_bounds__(256) attn_kernel(
    const float* __restrict__ q, const float* __restrict__ kcomp,
    const float* __restrict__ vcomp, const float* __restrict__ kwin,
    const float* __restrict__ vwin, const float* __restrict__ post,
    const float* __restrict__ posc, const float* __restrict__ rwb,
    const float* __restrict__ rrb,
    __nv_bfloat16* __restrict__ ohi, __nv_bfloat16* __restrict__ olo)
{
    extern __shared__ float sm[];
    float* qs   = sm;
    float* sc   = sm + ATT_OFF_SC;
    float* Dm   = sm + ATT_OFF_D;
    float* kb   = sm + ATT_OFF_KB;
    float* rwbs = sm + ATT_OFF_RW;
    float* rrbs = sm + ATT_OFF_RR;

    const int tid = threadIdx.x;
    const int wid = tid >> 5, lane = tid & 31;
    const int blk = blockIdx.x;
    const int qc = blk & 63;
    const int h  = (blk >> 6) & 15;
    const int b  = blk >> 10;
    const int l0 = qc * NCS;
    const int s0 = wid * 4;

    for (int i = tid; i < 32 * 16; i += 256) {
        int r = i >> 4, c4 = (i & 15) << 2;
        float4 v = *reinterpret_cast<const float4*>(q + (size_t)(b * NL + l0 + r) * ND + h * NDH + c4);
        *reinterpret_cast<float4*>(&qs[r * 64 + c4]) = v;
    }
    if (tid < 64) { rwbs[tid] = rwb[h * NDH + tid]; rrbs[tid] = rrb[h * NDH + tid]; }
    __syncthreads();

    // ---- Phase A: kcomp scores -> sc[:, 0:128]
    for (int i = tid; i < 128 * 16; i += 256) {
        int r = i >> 4, c4 = (i & 15) << 2;
        float4 v = *reinterpret_cast<const float4*>(kcomp + (size_t)(b * NNC + r) * ND + h * NDH + c4);
        float* d = &kb[r * ASTR + c4];
        d[0] = v.x; d[1] = v.y; d[2] = v.z; d[3] = v.w;
    }
    __syncthreads();
    {
        ull acc[4][4];
        #pragma unroll
        for (int s = 0; s < 4; s++)
            #pragma unroll
            for (int i = 0; i < 4; i++) acc[s][i] = 0ull;
        for (int dp = 0; dp < 32; dp++) {
            ull qv[4];
            #pragma unroll
            for (int s = 0; s < 4; s++)
                qv[s] = *reinterpret_cast<const ull*>(&qs[(s0 + s) * 64 + 2 * dp]);
            #pragma unroll
            for (int i = 0; i < 4; i++) {
                ull kv = *reinterpret_cast<const ull*>(&kb[(lane + 32 * i) * ASTR + 2 * dp]);
                #pragma unroll
                for (int s = 0; s < 4; s++) fma2(acc[s][i], qv[s], kv);
            }
        }
        #pragma unroll
        for (int s = 0; s < 4; s++)
            #pragma unroll
            for (int i = 0; i < 4; i++)
                sc[(s0 + s) * 256 + lane + 32 * i] = fold2(acc[s][i]);
    }
    __syncthreads();

    // ---- Phase P: rel-shift positional scores into sc[:,0:128] + mask
    {
        const int f0 = 64 + qc * 128;
        const int q2_0 = f0 / 129;
        const int base0 = f0 - 129 * q2_0;
        const int cstar = 129 - base0;

        for (int i = tid; i < 64 * 16; i += 256) {
            int r = i >> 4, c4 = (i & 15) << 2;
            int l = q2_0 * NCS + r;
            float4 v = make_float4(0.f, 0.f, 0.f, 0.f);
            if (l < NL) v = *reinterpret_cast<const float4*>(q + (size_t)(b * NL + l) * ND + h * NDH + c4);
            float* d = &Dm[r * ASTR + c4];
            d[0] = v.x; d[1] = v.y; d[2] = v.z; d[3] = v.w;
        }
        for (int i = tid; i < 129 * 16; i += 256) {
            int r = i >> 4, c4 = (i & 15) << 2;
            float4 v = make_float4(0.f, 0.f, 0.f, 0.f);
            if (r < 128) v = *reinterpret_cast<const float4*>(posc + (size_t)r * ND + h * NDH + c4);
            float* d = &kb[r * ASTR + c4];
            d[0] = v.x; d[1] = v.y; d[2] = v.z; d[3] = v.w;
        }
        __syncthreads();

        int pcrow[4]; bool seg1[4];
        #pragma unroll
        for (int i = 0; i < 4; i++) {
            int c = lane + 32 * i;
            seg1[i] = (c >= cstar);
            pcrow[i] = seg1[i] ? (c - cstar) : (base0 + c);
        }
        ull acc[4][4];
        #pragma unroll
        for (int s = 0; s < 4; s++)
            #pragma unroll
            for (int i = 0; i < 4; i++) acc[s][i] = 0ull;
        for (int dp = 0; dp < 32; dp++) {
            ull q0[4], q1[4];
            #pragma unroll
            for (int s = 0; s < 4; s++) {
                q0[s] = *reinterpret_cast<const ull*>(&Dm[(s0 + s) * ASTR + 2 * dp]);
                q1[s] = *reinterpret_cast<const ull*>(&Dm[(32 + s0 + s) * ASTR + 2 * dp]);
            }
            #pragma unroll
            for (int i = 0; i < 4; i++) {
                ull pv = *reinterpret_cast<const ull*>(&kb[pcrow[i] * ASTR + 2 * dp]);
                ull p0 = seg1[i] ? 0ull : pv;
                ull p1 = seg1[i] ? pv : 0ull;
                #pragma unroll
                for (int s = 0; s < 4; s++) {
                    fma2(acc[s][i], q0[s], p0);
                    fma2(acc[s][i], q1[s], p1);
                }
            }
        }
        #pragma unroll
        for (int s = 0; s < 4; s++)
            #pragma unroll
            for (int i = 0; i < 4; i++) {
                int c = lane + 32 * i;
                float v = sc[(s0 + s) * 256 + c] + fold2(acc[s][i]);
                if (c >= 64 && (c - 64) >= qc) v = -1e30f;
                sc[(s0 + s) * 256 + c] = v;
            }
    }
    __syncthreads();

    // ---- Phase B: post scores -> sc[:,128:256]
    for (int i = tid; i < 128 * 16; i += 256) {
        int r = i >> 4, c4 = (i & 15) << 2;
        float4 v = *reinterpret_cast<const float4*>(post + (size_t)r * ND + h * NDH + c4);
        float* d = &kb[r * ASTR + c4];
        d[0] = v.x; d[1] = v.y; d[2] = v.z; d[3] = v.w;
    }
    __syncthreads();
    {
        ull acc[4][4];
        #pragma unroll
        for (int s = 0; s < 4; s++)
            #pragma unroll
            for (int i = 0; i < 4; i++) acc[s][i] = 0ull;
        for (int dp = 0; dp < 32; dp++) {
            ull rr = *reinterpret_cast<const ull*>(&rrbs[2 * dp]);
            ull qv[4];
            #pragma unroll
            for (int s = 0; s < 4; s++)
                qv[s] = add2(*reinterpret_cast<const ull*>(&qs[(s0 + s) * 64 + 2 * dp]), rr);
            #pragma unroll
            for (int i = 0; i < 4; i++) {
                ull kv = *reinterpret_cast<const ull*>(&kb[(lane + 32 * i) * ASTR + 2 * dp]);
                #pragma unroll
                for (int s = 0; s < 4; s++) fma2(acc[s][i], qv[s], kv);
            }
        }
        #pragma unroll
        for (int s = 0; s < 4; s++)
            #pragma unroll
            for (int i = 0; i < 4; i++)
                sc[(s0 + s) * 256 + 128 + lane + 32 * i] = fold2(acc[s][i]);
    }
    __syncthreads();

    // ---- Phase C: band scores
    for (int i = tid; i < 160 * 16; i += 256) {
        int r = i >> 4, c4 = (i & 15) << 2;
        int idx = l0 + 1 + r;
        float4 v = make_float4(0.f, 0.f, 0.f, 0.f);
        if (idx < NWINROWS)
            v = *reinterpret_cast<const float4*>(kwin + (size_t)(b * NWINROWS + idx) * ND + h * NDH + c4);
        float* d = &kb[r * ASTR + c4];
        d[0] = v.x; d[1] = v.y; d[2] = v.z; d[3] = v.w;
    }
    __syncthreads();
    {
        ull acc[4][5];
        #pragma unroll
        for (int s = 0; s < 4; s++)
            #pragma unroll
            for (int i = 0; i < 5; i++) acc[s][i] = 0ull;
        for (int dp = 0; dp < 32; dp++) {
            ull rw = *reinterpret_cast<const ull*>(&rwbs[2 * dp]);
            ull qv[4];
            #pragma unroll
            for (int s = 0; s < 4; s++)
                qv[s] = add2(*reinterpret_cast<const ull*>(&qs[(s0 + s) * 64 + 2 * dp]), rw);
            #pragma unroll
            for (int i = 0; i < 5; i++) {
                ull kv = *reinterpret_cast<const ull*>(&kb[(lane + 32 * i) * ASTR + 2 * dp]);
                #pragma unroll
                for (int s = 0; s < 4; s++) fma2(acc[s][i], qv[s], kv);
            }
        }
        #pragma unroll
        for (int s = 0; s < 4; s++)
            #pragma unroll
            for (int i = 0; i < 5; i++)
                Dm[(s0 + s) * 160 + lane + 32 * i] = fold2(acc[s][i]);
    }
    __syncthreads();
    for (int i = tid; i < 32 * 128; i += 256) {
        int qi = i >> 7, j = i & 127;
        sc[qi * 256 + 128 + j] += Dm[qi * 160 + qi + j];
    }
    __syncthreads();

    // ---- softmax
    {
        const int w = tid >> 5, ln = tid & 31;
        for (int r = w; r < 32; r += 8) {
            float m = -1e30f;
            for (int c = ln; c < 256; c += 32) m = fmaxf(m, sc[r * 256 + c]);
            #pragma unroll
            for (int o = 16; o; o >>= 1) m = fmaxf(m, __shfl_xor_sync(0xffffffffu, m, o));
            float s = 0.f;
            for (int c = ln; c < 256; c += 32) {
                float e = __expf(sc[r * 256 + c] - m);
                sc[r * 256 + c] = e;
                s += e;
            }
            #pragma unroll
            for (int o = 16; o; o >>= 1) s += __shfl_xor_sync(0xffffffffu, s, o);
            float inv = 1.f / s;
            for (int c = ln; c < 256; c += 32) sc[r * 256 + c] *= inv;
        }
    }
    __syncthreads();

    // ---- Phase D: AV
    ull av[4] = {0ull, 0ull, 0ull, 0ull};
    for (int i = tid; i < 128 * 16; i += 256) {
        int r = i >> 4, c4 = (i & 15) << 2;
        float4 v = *reinterpret_cast<const float4*>(vcomp + (size_t)(b * NNC + r) * ND + h * NDH + c4);
        float* d = &kb[r * ASTR + c4];
        d[0] = v.x; d[1] = v.y; d[2] = v.z; d[3] = v.w;
    }
    __syncthreads();
    for (int c = 0; c < NNC; c++) {
        ull vv = *reinterpret_cast<const ull*>(&kb[c * ASTR + 2 * lane]);
        #pragma unroll
        for (int s = 0; s < 4; s++) {
            float sv = sc[(s0 + s) * 256 + c];
            fma2(av[s], pack2(sv), vv);
        }
    }
    __syncthreads();
    for (int i = tid; i < 160 * 16; i += 256) {
        int r = i >> 4, c4 = (i & 15) << 2;
        int idx = l0 + 1 + r;
        float4 v = make_float4(0.f, 0.f, 0.f, 0.f);
        if (idx < NWINROWS)
            v = *reinterpret_cast<const float4*>(vwin + (size_t)(b * NWINROWS + idx) * ND + h * NDH + c4);
        float* d = &kb[r * ASTR + c4];
        d[0] = v.x; d[1] = v.y; d[2] = v.z; d[3] = v.w;
    }
    __syncthreads();
    for (int r = 0; r < 160; r++) {
        ull vv = *reinterpret_cast<const ull*>(&kb[r * ASTR + 2 * lane]);
        #pragma unroll
        for (int s = 0; s < 4; s++) {
            int j = r - (s0 + s);
            if ((unsigned)j < 128u) {
                float sv = sc[(s0 + s) * 256 + 128 + j];
                fma2(av[s], pack2(sv), vv);
            }
        }
    }
    #pragma unroll
    for (int s = 0; s < 4; s++) {
        float2 o = unpack2(av[s]);
        const size_t base = (size_t)(b * NL + l0 + s0 + s) * ND + h * NDH + 2 * lane;
        __nv_bfloat16 h0 = __float2bfloat16(o.x), h1 = __float2bfloat16(o.y);
        __nv_bfloat16 l0b = __float2bfloat16(o.x - __bfloat162float(h0));
        __nv_bfloat16 l1b = __float2bfloat16(o.y - __bfloat162float(h1));
        *reinterpret_cast<__nv_bfloat162*>(ohi + base) = __nv_bfloat162(h0, h1);
        *reinterpret_cast<__nv_bfloat162*>(olo + base) = __nv_bfloat162(l0b, l1b);
    }
}

// ---------------- host launch ----------------
#define GETSYM(p, s) do { void* _t = nullptr; cudaGetSymbolAddress(&_t, s); (p) = decltype(p)(_t); } while (0)

static inline void tgemm_s(cudaStream_t st,
                           const __nv_bfloat16* Ahi, const __nv_bfloat16* Alo,
                           const __nv_bfloat16* Bhi, const __nv_bfloat16* Blo,
                           const float* bias, float* C0, float* C1, float* C2,
                           int M, int N, int K)
{
    dim3 grid(N / 128, M / 128);
    tgemm_kernel<<<grid, 256, TG_SMEM_TOTAL, st>>>(Ahi, Alo, Bhi, Blo, bias, C0, C1, C2, M, N, K);
}

extern "C" void kernel_launch(void* const* d_in, const int* in_sizes, int n_in,
                              void* d_out, int out_size)
{
    const float* h      = (const float*)d_in[0];
    const float* hcache = (const float*)d_in[1];
    const float* key_pe = (const float*)d_in[2];
    const float* poswin = (const float*)d_in[3];
    const float* Wq  = (const float*)d_in[4];
    const float* Wk  = (const float*)d_in[5];
    const float* Wv  = (const float*)d_in[6];
    const float* Wo  = (const float*)d_in[7];
    const float* Wd  = (const float*)d_in[8];
    const float* bd  = (const float*)d_in[9];
    const float* Wr  = (const float*)d_in[10];
    const float* br  = (const float*)d_in[11];
    const float* Wrc = (const float*)d_in[12];
    const float* brc = (const float*)d_in[13];
    const float* rrb = (const float*)d_in[14];
    const float* rwb = (const float*)d_in[15];
    const float* g_dp = (const float*)d_in[16];
    const float* b_dp = (const float*)d_in[17];
    const float* g_w  = (const float*)d_in[18];
    const float* b_w  = (const float*)d_in[19];
    float* outp = (float*)d_out;

    float *q, *kbp, *vbp, *sh, *shc, *sch, *schc, *hcm;
    float *hcmk, *hcmv, *kcomp, *vcomp, *hwk, *hwv, *kwin, *vwin, *post, *posc;
    GETSYM(q, g_q); GETSYM(kbp, g_kbp); GETSYM(vbp, g_vbp);
    GETSYM(sh, g_sh); GETSYM(shc, g_shc); GETSYM(sch, g_sch); GETSYM(schc, g_schc);
    GETSYM(hcm, g_hcm);
    GETSYM(hcmk, g_hcmk); GETSYM(hcmv, g_hcmv);
    GETSYM(kcomp, g_kcomp); GETSYM(vcomp, g_vcomp);
    GETSYM(hwk, g_hwk); GETSYM(hwv, g_hwv);
    GETSYM(kwin, g_kwin); GETSYM(vwin, g_vwin);
    GETSYM(post, g_post); GETSYM(posc, g_posc);

    __nv_bfloat16 *ahi, *alo, *xhi, *xlo, *yhi, *ylo, *phi, *plo, *ehi, *elo;
    __nv_bfloat16 *wqkvh, *wqkvl, *woh, *wol, *wrh, *wrl, *wrch, *wrcl;
    GETSYM(ahi, g_ahi); GETSYM(alo, g_alo);
    GETSYM(xhi, g_xhi); GETSYM(xlo, g_xlo);
    GETSYM(yhi, g_yhi); GETSYM(ylo, g_ylo);
    GETSYM(phi, g_phi); GETSYM(plo, g_plo);
    GETSYM(ehi, g_ehi); GETSYM(elo, g_elo);
    GETSYM(wqkvh, g_wqkvh); GETSYM(wqkvl, g_wqkvl);
    GETSYM(woh, g_woh); GETSYM(wol, g_wol);
    GETSYM(wrh, g_wrh); GETSYM(wrl, g_wrl); GETSYM(wrch, g_wrch); GETSYM(wrcl, g_wrcl);

    const int ATTN_SMEM = ATT_SMEM_F * (int)sizeof(float);
    cudaFuncSetAttribute(attn_kernel, cudaFuncAttributeMaxDynamicSharedMemorySize, ATTN_SMEM);
    cudaFuncSetAttribute(tgemm_kernel, cudaFuncAttributeMaxDynamicSharedMemorySize, TG_SMEM_TOTAL);

    // one-time stream/event creation (host resources only; no device memory)
    static cudaStream_t s1 = nullptr, s2 = nullptr;
    static cudaEvent_t evRoot = nullptr, evWk = nullptr, evSch = nullptr,
                       evQKV = nullptr, ev1 = nullptr, ev2 = nullptr;
    if (!s1) {
        cudaStreamCreateWithFlags(&s1, cudaStreamNonBlocking);
        cudaStreamCreateWithFlags(&s2, cudaStreamNonBlocking);
        cudaEventCreateWithFlags(&evRoot, cudaEventDisableTiming);
        cudaEventCreateWithFlags(&evWk,   cudaEventDisableTiming);
        cudaEventCreateWithFlags(&evSch,  cudaEventDisableTiming);
        cudaEventCreateWithFlags(&evQKV,  cudaEventDisableTiming);
        cudaEventCreateWithFlags(&ev1,    cudaEventDisableTiming);
        cudaEventCreateWithFlags(&ev2,    cudaEventDisableTiming);
    }

    const int M = NB * NL;   // 8192
    const int WSZ = ND * ND;
    const cudaStream_t s0 = 0;
    dim3 wg(32, 32);

    // ---- fork side streams from the launch stream (record precedes all waits)
    cudaEventRecord(evRoot, s0);
    cudaStreamWaitEvent(s1, evRoot, 0);
    cudaStreamWaitEvent(s2, evRoot, 0);

    // ---- s1 (part 1): both chunk-score GEMVs + softmaxes, batched
    gemv16x2_kernel<<<2 * (M / 64), 256, 0, s1>>>(h, hcache, Wd, bd, sh, shc, M / 64);
    chunk_softmax2_kernel<<<2 * NB * NNQ, 512, 0, s1>>>(sh, shc, sch, schc, NB * NNQ);
    cudaEventRecord(evSch, s1);

    // ---- s2 (part 1): independent splits + positional GEMMs
    wsplit_kernel<<<wg, 256, 0, s2>>>(Wr,  wrh,  wrl,  1.f);
    wsplit_kernel<<<wg, 256, 0, s2>>>(Wrc, wrch, wrcl, 1.f);
    split_kernel<<<NW, 256, 0, s2>>>(poswin, phi, plo, NW, 0, 0);
    split_kernel<<<NNC, 256, 0, s2>>>(key_pe, ehi, elo, NNC, 0, 0);
    tgemm_s(s2, phi, plo, wrh, wrl, br, post, nullptr, nullptr, NW, ND, ND);
    tgemm_s(s2, ehi, elo, wrch, wrcl, brc, posc, nullptr, nullptr, NNC, ND, ND);
    split_kernel<<<NB * NW, 256, 0, s2>>>(hcache, yhi, ylo, NW, NCACHE, NCACHE - NW);

    // ---- s1 (part 2): hcache compress + split
    compress_kernel<<<NB * NNQ, 256, 0, s1>>>(hcache, schc, hcm, NCACHE);
    split_kernel<<<NB * NNQ, 256, 0, s1>>>(hcm, xhi, xlo, NB * NNQ, 0, 0);

    // ================= s0: main chain =================
    wsplit_kernel<<<wg, 256, 0, s0>>>(Wq,  wqkvh,           wqkvl,           0.125f);
    wsplit_kernel<<<wg, 256, 0, s0>>>(Wk,  wqkvh + WSZ,     wqkvl + WSZ,     1.f);
    wsplit_kernel<<<wg, 256, 0, s0>>>(Wv,  wqkvh + 2 * WSZ, wqkvl + 2 * WSZ, 1.f);
    cudaEventRecord(evWk, s0);                 // Wk/Wv splits ready
    wsplit_kernel<<<wg, 256, 0, s0>>>(Wo,  woh,  wol,  1.f);
    split_kernel<<<M, 256, 0, s0>>>(h, ahi, alo, M, 0, 0);

    // fused q/k/v projection of h (N=3072)
    tgemm_s(s0, ahi, alo, wqkvh, wqkvl, nullptr, q, kbp, vbp, M, 3 * ND, ND);
    cudaEventRecord(evQKV, s0);                // kbp/vbp ready (for s2 window LNs)

    // fused compress+LN of block K/V -> kcomp/vcomp rows 64+ (needs sch)
    cudaStreamWaitEvent(s0, evSch, 0);
    {
        dim3 cg(NB * NNQ, 2);
        compress_ln_kernel<<<cg, 256, 0, s0>>>(kbp, vbp, sch, kcomp, vcomp, g_dp, b_dp);
    }

    // ---- s1 (part 3): cache K/V GEMM (needs evWk)
    cudaStreamWaitEvent(s1, evWk, 0);
    tgemm_s(s1, xhi, xlo, wqkvh + WSZ, wqkvl + WSZ, nullptr, hcmk, hcmv, nullptr,
            NB * NNQ, 2 * ND, ND);
    {
        dim3 lg(NB * NNQ, 2);
        ln2_kernel<<<lg, 256, 0, s1>>>(hcmk, hcmv, kcomp, vcomp, g_dp, b_dp, NNQ, NNC, 0);
    }
    cudaEventRecord(ev1, s1);

    // ---- s2 (part 2): window-cache K/V GEMM + ALL window LNs (dual launches)
    cudaStreamWaitEvent(s2, evWk, 0);
    tgemm_s(s2, yhi, ylo, wqkvh + WSZ, wqkvl + WSZ, nullptr, hwk, hwv, nullptr,
            NB * NW, 2 * ND, ND);
    {
        dim3 lg(NB * NW, 2);
        ln2_kernel<<<lg, 256, 0, s2>>>(hwk, hwv, kwin, vwin, g_w, b_w, NW, NWINROWS, 0);
    }
    cudaStreamWaitEvent(s2, evQKV, 0);
    {
        dim3 lg(M, 2);
        ln2_kernel<<<lg, 256, 0, s2>>>(kbp, vbp, kwin, vwin, g_w, b_w, NL, NWINROWS, NW);
    }
    cudaEventRecord(ev2, s2);

    // ---- join side streams before attention
    cudaStreamWaitEvent(s0, ev1, 0);
    cudaStreamWaitEvent(s0, ev2, 0);

    // fused attention (rel-shift positional computed in-kernel; bf16 hi/lo out)
    attn_kernel<<<NB * NH * NNQ, 256, ATTN_SMEM, s0>>>(q, kcomp, vcomp, kwin, vwin,
                                                       post, posc, rwb, rrb, ahi, alo);

    // output projection
    tgemm_s(s0, ahi, alo, woh, wol, nullptr, outp, nullptr, nullptr, M, ND, ND);
}

// round 13
// speedup vs baseline: 1.0403x; 1.0403x over previous
#include <cuda_runtime.h>
#include <cuda_bf16.h>
#include <math.h>
#include <stdint.h>

// ---------------- problem constants ----------------
#define NB 4
#define NL 2048
#define ND 1024
#define NH 16
#define NDH 64
#define NW 128
#define NCS 32
#define NNC 128          // total compressed keys (64 cache + 64 block)
#define NNQ 64           // L / CS
#define NCACHE 2048
#define NWINROWS (NW + NL)   // 2176

typedef unsigned long long ull;

// ---------------- scratch buffers (device globals; no mallocs allowed) ----------------
__device__ float g_q[NB*NL*ND];
__device__ float g_kbp[NB*NL*ND];
__device__ float g_vbp[NB*NL*ND];
__device__ float g_sh[NB*NL*NH];
__device__ float g_shc[NB*NCACHE*NH];
__device__ float g_sch[NB*NH*NNQ*NCS];
__device__ float g_schc[NB*NH*NNQ*NCS];
__device__ float g_hcm[NB*NNQ*ND];
__device__ float g_hcmk[NB*NNQ*ND];
__device__ float g_hcmv[NB*NNQ*ND];
__device__ float g_kcomp[NB*NNC*ND];
__device__ float g_vcomp[NB*NNC*ND];
__device__ float g_hwk[NB*NW*ND];
__device__ float g_hwv[NB*NW*ND];
__device__ float g_kwin[NB*NWINROWS*ND];
__device__ float g_vwin[NB*NWINROWS*ND];
__device__ float g_post[NW*ND];
__device__ float g_posc[NNC*ND];

// bf16 hi/lo split buffers (per-chain to avoid false dependencies)
__device__ __nv_bfloat16 g_ahi[NB*NL*ND];
__device__ __nv_bfloat16 g_alo[NB*NL*ND];
__device__ __nv_bfloat16 g_xhi[256*ND],  g_xlo[256*ND];    // hcm (s1)
__device__ __nv_bfloat16 g_yhi[512*ND],  g_ylo[512*ND];    // hw (s2)
__device__ __nv_bfloat16 g_phi[NW*ND],   g_plo[NW*ND];     // poswin (s2)
__device__ __nv_bfloat16 g_ehi[NNC*ND],  g_elo[NNC*ND];    // key_pe (s2)
__device__ __nv_bfloat16 g_wqkvh[3*ND*ND], g_wqkvl[3*ND*ND];   // rows: q(scaled)|k|v
__device__ __nv_bfloat16 g_woh[ND*ND], g_wol[ND*ND];
__device__ __nv_bfloat16 g_wrh[ND*ND], g_wrl[ND*ND];
__device__ __nv_bfloat16 g_wrch[ND*ND], g_wrcl[ND*ND];

// ================= low-level helpers =================
__device__ __forceinline__ uint32_t smem_u32(const void* p) {
    uint32_t a;
    asm("{ .reg .u64 t; cvta.to.shared.u64 t, %1; cvt.u32.u64 %0, t; }" : "=r"(a) : "l"(p));
    return a;
}
__device__ __forceinline__ void ldm_x4(uint32_t& r0, uint32_t& r1, uint32_t& r2, uint32_t& r3,
                                       uint32_t addr) {
    asm volatile("ldmatrix.sync.aligned.m8n8.x4.shared.b16 {%0,%1,%2,%3}, [%4];"
                 : "=r"(r0), "=r"(r1), "=r"(r2), "=r"(r3) : "r"(addr));
}
__device__ __forceinline__ void mma_bf16(float* c, const uint32_t* a, uint32_t b0, uint32_t b1) {
    asm volatile("mma.sync.aligned.m16n8k16.row.col.f32.bf16.bf16.f32 "
                 "{%0,%1,%2,%3}, {%4,%5,%6,%7}, {%8,%9}, {%0,%1,%2,%3};"
                 : "+f"(c[0]), "+f"(c[1]), "+f"(c[2]), "+f"(c[3])
                 : "r"(a[0]), "r"(a[1]), "r"(a[2]), "r"(a[3]), "r"(b0), "r"(b1));
}
#define CP16(dst, src) \
    asm volatile("cp.async.cg.shared.global [%0], [%1], 16;" :: "r"(dst), "l"(src))
#define CP_COMMIT() asm volatile("cp.async.commit_group;" ::: "memory")
#define CP_WAIT1()  asm volatile("cp.async.wait_group 1;" ::: "memory")

// packed fp32x2 math (SASS FFMA2 — PTX-only)
__device__ __forceinline__ void fma2(ull& d, ull a, ull b) {
    asm("fma.rn.f32x2 %0, %1, %2, %0;" : "+l"(d) : "l"(a), "l"(b));
}
__device__ __forceinline__ ull add2(ull a, ull b) {
    ull r; asm("add.rn.f32x2 %0, %1, %2;" : "=l"(r) : "l"(a), "l"(b)); return r;
}
__device__ __forceinline__ ull pack2(float x) {
    ull r; asm("mov.b64 %0, {%1, %1};" : "=l"(r) : "f"(x)); return r;
}
__device__ __forceinline__ float fold2(ull v) {
    float lo, hi; asm("mov.b64 {%0, %1}, %2;" : "=f"(lo), "=f"(hi) : "l"(v)); return lo + hi;
}
__device__ __forceinline__ float2 unpack2(ull v) {
    float2 r; asm("mov.b64 {%0, %1}, %2;" : "=f"(r.x), "=f"(r.y) : "l"(v)); return r;
}

// ================= tensor-core GEMM (double-buffered, 2 CTAs/SM) =================
#define TSTR 40
#define TILE_B (128 * TSTR * 2)
#define BUF_B  (4 * TILE_B)
#define TG_SMEM_TOTAL (2 * BUF_B)      // 81920 -> 2 CTAs/SM

__global__ void __launch_bounds__(256)
tgemm_kernel(const __nv_bfloat16* __restrict__ Ahi, const __nv_bfloat16* __restrict__ Alo,
             const __nv_bfloat16* __restrict__ Bhi, const __nv_bfloat16* __restrict__ Blo,
             const float* __restrict__ bias,
             float* __restrict__ C0, float* __restrict__ C1, float* __restrict__ C2,
             int M, int N, int K)
{
    extern __shared__ char smc[];
    const uint32_t sbase = smem_u32(smc);
    const int tid = threadIdx.x;
    const int wid = tid >> 5, lane = tid & 31;
    const int row0 = blockIdx.y << 7;
    const int col0 = blockIdx.x << 7;
    const int wm = wid >> 1;
    const int wn = wid & 1;

    const __nv_bfloat16* srcs[4] = {Ahi, Alo, Bhi, Blo};
    const int nch = K >> 5;

    {
        #pragma unroll
        for (int it = 0; it < 8; it++) {
            int id = tid + it * 256;
            int t = id >> 9;
            int j = id & 511;
            int r = j >> 2;
            int ch = j & 3;
            long grow = (t < 2) ? (long)(row0 + r) : (long)(col0 + r);
            CP16(sbase + t * TILE_B + r * (TSTR * 2) + ch * 16,
                 srcs[t] + grow * K + ch * 8);
        }
        CP_COMMIT();
    }

    float acc[2][8][4];
    #pragma unroll
    for (int mt = 0; mt < 2; mt++)
        #pragma unroll
        for (int nt = 0; nt < 8; nt++)
            #pragma unroll
            for (int f = 0; f < 4; f++) acc[mt][nt][f] = 0.f;

    const int lrow = lane & 15;
    const int lcol = (lane >> 4) * 16;

    for (int kc = 0; kc < nch; kc++) {
        const uint32_t buf = sbase + (kc & 1) * BUF_B;
        if (kc + 1 < nch) {
            const long kb = (long)(kc + 1) << 5;
            const uint32_t nbuf = sbase + ((kc + 1) & 1) * BUF_B;
            #pragma unroll
            for (int it = 0; it < 8; it++) {
                int id = tid + it * 256;
                int t = id >> 9;
                int j = id & 511;
                int r = j >> 2;
                int ch = j & 3;
                long grow = (t < 2) ? (long)(row0 + r) : (long)(col0 + r);
                CP16(nbuf + t * TILE_B + r * (TSTR * 2) + ch * 16,
                     srcs[t] + grow * K + kb + ch * 8);
            }
        }
        CP_COMMIT();
        CP_WAIT1();
        __syncthreads();

        const uint32_t aBase = buf + (wm * 32 + lrow) * (TSTR * 2) + lcol;
        const uint32_t bBase = buf + 2 * TILE_B + (wn * 64 + lrow) * (TSTR * 2) + lcol;

        #pragma unroll
        for (int kk = 0; kk < 2; kk++) {
            const uint32_t ko = kk * 32;
            uint32_t ah[2][4], al[2][4];
            #pragma unroll
            for (int mt = 0; mt < 2; mt++) {
                ldm_x4(ah[mt][0], ah[mt][1], ah[mt][2], ah[mt][3],
                       aBase + mt * 16 * (TSTR * 2) + ko);
                ldm_x4(al[mt][0], al[mt][1], al[mt][2], al[mt][3],
                       aBase + TILE_B + mt * 16 * (TSTR * 2) + ko);
            }
            #pragma unroll
            for (int np = 0; np < 4; np++) {
                uint32_t bh0, bh1, bh2, bh3, bl0, bl1, bl2, bl3;
                ldm_x4(bh0, bh1, bh2, bh3, bBase + np * 16 * (TSTR * 2) + ko);
                ldm_x4(bl0, bl1, bl2, bl3, bBase + TILE_B + np * 16 * (TSTR * 2) + ko);
                #pragma unroll
                for (int mt = 0; mt < 2; mt++) {
                    mma_bf16(acc[mt][np * 2],     ah[mt], bh0, bh2);
                    mma_bf16(acc[mt][np * 2 + 1], ah[mt], bh1, bh3);
                    mma_bf16(acc[mt][np * 2],     al[mt], bh0, bh2);
                    mma_bf16(acc[mt][np * 2 + 1], al[mt], bh1, bh3);
                    mma_bf16(acc[mt][np * 2],     ah[mt], bl0, bl2);
                    mma_bf16(acc[mt][np * 2 + 1], ah[mt], bl1, bl3);
                }
            }
        }
        __syncthreads();
    }

    float* Cs[3] = {C0, C1, C2};
    const int g = lane >> 2, tig = lane & 3;
    #pragma unroll
    for (int mt = 0; mt < 2; mt++) {
        const long r0g = row0 + wm * 32 + mt * 16 + g;
        #pragma unroll
        for (int nt = 0; nt < 8; nt++) {
            const int cN = col0 + wn * 64 + nt * 8 + tig * 2;
            float* Cp = Cs[cN >> 10];
            const int cc = cN & 1023;
            float b0 = 0.f, b1 = 0.f;
            if (bias) { b0 = bias[cN]; b1 = bias[cN + 1]; }
            float2 o0 = make_float2(acc[mt][nt][0] + b0, acc[mt][nt][1] + b1);
            float2 o1 = make_float2(acc[mt][nt][2] + b0, acc[mt][nt][3] + b1);
            *reinterpret_cast<float2*>(Cp + r0g * 1024 + cc)       = o0;
            *reinterpret_cast<float2*>(Cp + (r0g + 8) * 1024 + cc) = o1;
        }
    }
}

// ================= fp32 -> bf16 hi/lo split (row remap supported) =================
__global__ void split_kernel(const float* __restrict__ in, __nv_bfloat16* __restrict__ hi,
                             __nv_bfloat16* __restrict__ lo, int rpb, long bstride, long off)
{
    const int r = blockIdx.x;
    const long phys = (long)(r / rpb) * bstride + off + (r % rpb);
    const int c = threadIdx.x * 4;
    float4 v = *reinterpret_cast<const float4*>(in + phys * ND + c);
    __nv_bfloat16 h0 = __float2bfloat16(v.x), h1 = __float2bfloat16(v.y);
    __nv_bfloat16 h2 = __float2bfloat16(v.z), h3 = __float2bfloat16(v.w);
    __nv_bfloat16 l0 = __float2bfloat16(v.x - __bfloat162float(h0));
    __nv_bfloat16 l1 = __float2bfloat16(v.y - __bfloat162float(h1));
    __nv_bfloat16 l2 = __float2bfloat16(v.z - __bfloat162float(h2));
    __nv_bfloat16 l3 = __float2bfloat16(v.w - __bfloat162float(h3));
    __nv_bfloat162 hp0(h0, h1), hp1(h2, h3), lp0(l0, l1), lp1(l2, l3);
    *reinterpret_cast<__nv_bfloat162*>(hi + (long)r * ND + c)     = hp0;
    *reinterpret_cast<__nv_bfloat162*>(hi + (long)r * ND + c + 2) = hp1;
    *reinterpret_cast<__nv_bfloat162*>(lo + (long)r * ND + c)     = lp0;
    *reinterpret_cast<__nv_bfloat162*>(lo + (long)r * ND + c + 2) = lp1;
}

// ================= weight transpose + split (with scale): W[K,N] -> [N,K] =================
__global__ void wsplit_kernel(const float* __restrict__ W, __nv_bfloat16* __restrict__ hiT,
                              __nv_bfloat16* __restrict__ loT, float scale)
{
    __shared__ float t[32][33];
    const int tx = threadIdx.x & 31, ty = threadIdx.x >> 5;
    const int k0 = blockIdx.y * 32, n0 = blockIdx.x * 32;
    #pragma unroll
    for (int i = 0; i < 32; i += 8)
        t[ty + i][tx] = W[(long)(k0 + ty + i) * ND + n0 + tx];
    __syncthreads();
    #pragma unroll
    for (int i = 0; i < 32; i += 8) {
        float v = t[tx][ty + i] * scale;
        __nv_bfloat16 h = __float2bfloat16(v);
        __nv_bfloat16 l = __float2bfloat16(v - __bfloat162float(h));
        hiT[(long)(n0 + ty + i) * ND + k0 + tx] = h;
        loT[(long)(n0 + ty + i) * ND + k0 + tx] = l;
    }
}

// ================= N=16 GEMV =================
__global__ void gemv16_kernel(const float* __restrict__ x, const float* __restrict__ Wd,
                              const float* __restrict__ bd, float* __restrict__ out)
{
    __shared__ float As[64][65];
    __shared__ float Ws[64][16];
    const int tid = threadIdx.x;
    const int row0 = blockIdx.x * 64;
    const int col = tid & 15, rg = tid >> 4;
    float acc[4] = {0.f, 0.f, 0.f, 0.f};

    for (int k0 = 0; k0 < ND; k0 += 64) {
        #pragma unroll
        for (int it = 0; it < 16; it++) {
            int i = tid + it * 256;
            int r = i >> 6, c = i & 63;
            As[r][c] = x[(long)(row0 + r) * ND + k0 + c];
        }
        #pragma unroll
        for (int it = 0; it < 4; it++) {
            int i = tid + it * 256;
            int k = i >> 4, c = i & 15;
            Ws[k][c] = Wd[(long)(k0 + k) * NH + c];
        }
        __syncthreads();
        #pragma unroll 8
        for (int k = 0; k < 64; k++) {
            float w = Ws[k][col];
            #pragma unroll
            for (int j = 0; j < 4; j++) acc[j] += As[rg * 4 + j][k] * w;
        }
        __syncthreads();
    }
    #pragma unroll
    for (int j = 0; j < 4; j++)
        out[(long)(row0 + rg * 4 + j) * NH + col] = acc[j] + bd[col];
}

// ---------------- per-chunk, per-head softmax of raw scores ----------------
__global__ void chunk_softmax_kernel(const float* __restrict__ s_in, float* __restrict__ sc_out,
                                     int Lx)
{
    const int ncx = Lx / NCS;
    const int bc = blockIdx.x;
    const int b = bc / ncx, c = bc % ncx;
    const int h = threadIdx.x >> 5, s = threadIdx.x & 31;

    float v = s_in[(size_t)(b * Lx + c * NCS + s) * NH + h];
    float m = v;
    #pragma unroll
    for (int o = 16; o; o >>= 1) m = fmaxf(m, __shfl_xor_sync(0xffffffffu, m, o));
    float e = __expf(v - m);
    float sum = e;
    #pragma unroll
    for (int o = 16; o; o >>= 1) sum += __shfl_xor_sync(0xffffffffu, sum, o);
    sc_out[((size_t)(b * NH + h) * ncx + c) * NCS + s] = e / sum;
}

// ---------------- compress (plain, for hcm path) ----------------
__global__ void compress_kernel(const float* __restrict__ x, const float* __restrict__ sc,
                                float* __restrict__ out, int Lx)
{
    const int ncx = Lx / NCS;
    const int b = blockIdx.x / ncx, c = blockIdx.x % ncx;
    __shared__ float w[NH][NCS];
    const int tid = threadIdx.x;
    for (int i = tid; i < NH * NCS; i += 256) {
        int h = i >> 5, s = i & 31;
        w[h][s] = sc[((size_t)(b * NH + h) * ncx + c) * NCS + s];
    }
    __syncthreads();

    const int col = tid * 4;
    const int h = col >> 6;
    float4 acc = make_float4(0.f, 0.f, 0.f, 0.f);
    #pragma unroll 4
    for (int s = 0; s < NCS; s++) {
        float ws = w[h][s];
        float4 xv = *reinterpret_cast<const float4*>(x + (size_t)(b * Lx + c * NCS + s) * ND + col);
        acc.x += ws * xv.x; acc.y += ws * xv.y; acc.z += ws * xv.z; acc.w += ws * xv.w;
    }
    *reinterpret_cast<float4*>(out + (size_t)(b * ncx + c) * ND + col) = acc;
}

// ---------------- fused compress + LayerNorm (block K/V -> kcomp/vcomp rows 64+) ----------
__global__ void compress_ln_kernel(const float* __restrict__ xk, const float* __restrict__ xv,
                                   const float* __restrict__ sc,
                                   float* __restrict__ outk, float* __restrict__ outv,
                                   const float* __restrict__ g, const float* __restrict__ be)
{
    const int b = blockIdx.x / NNQ, c = blockIdx.x % NNQ;
    const float* x = blockIdx.y ? xv : xk;
    float* out = blockIdx.y ? outv : outk;

    __shared__ float w[NH][NCS];
    __shared__ float red[32];
    const int tid = threadIdx.x;
    for (int i = tid; i < NH * NCS; i += 256) {
        int h = i >> 5, s = i & 31;
        w[h][s] = sc[((size_t)(b * NH + h) * NNQ + c) * NCS + s];
    }
    __syncthreads();

    const int col = tid * 4;
    const int h = col >> 6;
    float4 acc = make_float4(0.f, 0.f, 0.f, 0.f);
    #pragma unroll 4
    for (int s = 0; s < NCS; s++) {
        float ws = w[h][s];
        float4 xvv = *reinterpret_cast<const float4*>(x + (size_t)(b * NL + c * NCS + s) * ND + col);
        acc.x += ws * xvv.x; acc.y += ws * xvv.y; acc.z += ws * xvv.z; acc.w += ws * xvv.w;
    }

    float s1 = acc.x + acc.y + acc.z + acc.w;
    #pragma unroll
    for (int o = 16; o; o >>= 1) s1 += __shfl_xor_sync(0xffffffffu, s1, o);
    if ((tid & 31) == 0) red[tid >> 5] = s1;
    __syncthreads();
    if (tid < 32) {
        float t = (tid < 8) ? red[tid] : 0.f;
        #pragma unroll
        for (int o = 4; o; o >>= 1) t += __shfl_xor_sync(0xffffffffu, t, o);
        if (tid == 0) red[0] = t;
    }
    __syncthreads();
    float mean = red[0] * (1.f / ND);
    __syncthreads();

    float d0 = acc.x - mean, d1 = acc.y - mean, d2 = acc.z - mean, d3 = acc.w - mean;
    float s2 = d0*d0 + d1*d1 + d2*d2 + d3*d3;
    #pragma unroll
    for (int o = 16; o; o >>= 1) s2 += __shfl_xor_sync(0xffffffffu, s2, o);
    if ((tid & 31) == 0) red[tid >> 5] = s2;
    __syncthreads();
    if (tid < 32) {
        float t = (tid < 8) ? red[tid] : 0.f;
        #pragma unroll
        for (int o = 4; o; o >>= 1) t += __shfl_xor_sync(0xffffffffu, t, o);
        if (tid == 0) red[0] = t;
    }
    __syncthreads();
    float rstd = rsqrtf(red[0] * (1.f / ND) + 1e-5f);

    const long orow = (long)b * NNC + 64 + c;
    float4 ov;
    ov.x = d0 * rstd * g[col + 0] + be[col + 0];
    ov.y = d1 * rstd * g[col + 1] + be[col + 1];
    ov.z = d2 * rstd * g[col + 2] + be[col + 2];
    ov.w = d3 * rstd * g[col + 3] + be[col + 3];
    *reinterpret_cast<float4*>(out + orow * ND + col) = ov;
}

// ---------------- dual row LayerNorm: blockIdx.y picks (in1->out1) or (in2->out2) ---------
__global__ void ln2_kernel(const float* __restrict__ in1, const float* __restrict__ in2,
                           float* __restrict__ out1, float* __restrict__ out2,
                           const float* __restrict__ g, const float* __restrict__ be,
                           int rpb, int out_bstride, int out_off)
{
    __shared__ float red[32];
    const int r = blockIdx.x;
    const int tid = threadIdx.x;
    const float* in = blockIdx.y ? in2 : in1;
    float* out = blockIdx.y ? out2 : out1;

    const float* x = in + (size_t)r * ND;
    float4 v = *reinterpret_cast<const float4*>(x + tid * 4);

    float s = v.x + v.y + v.z + v.w;
    #pragma unroll
    for (int o = 16; o; o >>= 1) s += __shfl_xor_sync(0xffffffffu, s, o);
    if ((tid & 31) == 0) red[tid >> 5] = s;
    __syncthreads();
    if (tid < 32) {
        float t = (tid < 8) ? red[tid] : 0.f;
        #pragma unroll
        for (int o = 4; o; o >>= 1) t += __shfl_xor_sync(0xffffffffu, t, o);
        if (tid == 0) red[0] = t;
    }
    __syncthreads();
    float mean = red[0] * (1.f / ND);
    __syncthreads();

    float d0 = v.x - mean, d1 = v.y - mean, d2 = v.z - mean, d3 = v.w - mean;
    float s2 = d0*d0 + d1*d1 + d2*d2 + d3*d3;
    #pragma unroll
    for (int o = 16; o; o >>= 1) s2 += __shfl_xor_sync(0xffffffffu, s2, o);
    if ((tid & 31) == 0) red[tid >> 5] = s2;
    __syncthreads();
    if (tid < 32) {
        float t = (tid < 8) ? red[tid] : 0.f;
        #pragma unroll
        for (int o = 4; o; o >>= 1) t += __shfl_xor_sync(0xffffffffu, t, o);
        if (tid == 0) red[0] = t;
    }
    __syncthreads();
    float rstd = rsqrtf(red[0] * (1.f / ND) + 1e-5f);

    const int orow = (r / rpb) * out_bstride + out_off + (r % rpb);
    const int c = tid * 4;
    float4 ov;
    ov.x = d0 * rstd * g[c + 0] + be[c + 0];
    ov.y = d1 * rstd * g[c + 1] + be[c + 1];
    ov.z = d2 * rstd * g[c + 2] + be[c + 2];
    ov.w = d3 * rstd * g[c + 3] + be[c + 3];
    *reinterpret_cast<float4*>(out + (size_t)orow * ND + c) = ov;
}

// ---------------- fused attention: rel-shift pos + scores + softmax + AV ----------------
#define ASTR 66
#define ATT_OFF_SC 2048
#define ATT_OFF_D  10240
#define ATT_OFF_KB 15360
#define ATT_OFF_RW 25920
#define ATT_OFF_RR 25984
#define ATT_SMEM_F 26048

__global__ void __launch_bounds__(256) attn_kernel(
    const float* __restrict__ q, const float* __restrict__ kcomp,
    const float* __restrict__ vcomp, const float* __restrict__ kwin,
    const float* __restrict__ vwin, const float* __restrict__ post,
    const float* __restrict__ posc, const float* __restrict__ rwb,
    const float* __restrict__ rrb,
    __nv_bfloat16* __restrict__ ohi, __nv_bfloat16* __restrict__ olo)
{
    extern __shared__ float sm[];
    float* qs   = sm;
    float* sc   = sm + ATT_OFF_SC;
    float* Dm   = sm + ATT_OFF_D;
    float* kb   = sm + ATT_OFF_KB;
    float* rwbs = sm + ATT_OFF_RW;
    float* rrbs = sm + ATT_OFF_RR;

    const int tid = threadIdx.x;
    const int wid = tid >> 5, lane = tid & 31;
    const int blk = blockIdx.x;
    const int qc = blk & 63;
    const int h  = (blk >> 6) & 15;
    const int b  = blk >> 10;
    const int l0 = qc * NCS;
    const int s0 = wid * 4;

    for (int i = tid; i < 32 * 16; i += 256) {
        int r = i >> 4, c4 = (i & 15) << 2;
        float4 v = *reinterpret_cast<const float4*>(q + (size_t)(b * NL + l0 + r) * ND + h * NDH + c4);
        *reinterpret_cast<float4*>(&qs[r * 64 + c4]) = v;
    }
    if (tid < 64) { rwbs[tid] = rwb[h * NDH + tid]; rrbs[tid] = rrb[h * NDH + tid]; }
    __syncthreads();

    // ---- Phase A: kcomp scores -> sc[:, 0:128]
    for (int i = tid; i < 128 * 16; i += 256) {
        int r = i >> 4, c4 = (i & 15) << 2;
        float4 v = *reinterpret_cast<const float4*>(kcomp + (size_t)(b * NNC + r) * ND + h * NDH + c4);
        float* d = &kb[r * ASTR + c4];
        d[0] = v.x; d[1] = v.y; d[2] = v.z; d[3] = v.w;
    }
    __syncthreads();
    {
        ull acc[4][4];
        #pragma unroll
        for (int s = 0; s < 4; s++)
            #pragma unroll
            for (int i = 0; i < 4; i++) acc[s][i] = 0ull;
        for (int dp = 0; dp < 32; dp++) {
            ull qv[4];
            #pragma unroll
            for (int s = 0; s < 4; s++)
                qv[s] = *reinterpret_cast<const ull*>(&qs[(s0 + s) * 64 + 2 * dp]);
            #pragma unroll
            for (int i = 0; i < 4; i++) {
                ull kv = *reinterpret_cast<const ull*>(&kb[(lane + 32 * i) * ASTR + 2 * dp]);
                #pragma unroll
                for (int s = 0; s < 4; s++) fma2(acc[s][i], qv[s], kv);
            }
        }
        #pragma unroll
        for (int s = 0; s < 4; s++)
            #pragma unroll
            for (int i = 0; i < 4; i++)
                sc[(s0 + s) * 256 + lane + 32 * i] = fold2(acc[s][i]);
    }
    __syncthreads();

    // ---- Phase P: rel-shift positional scores into sc[:,0:128] + mask
    {
        const int f0 = 64 + qc * 128;
        const int q2_0 = f0 / 129;
        const int base0 = f0 - 129 * q2_0;
        const int cstar = 129 - base0;

        for (int i = tid; i < 64 * 16; i += 256) {
            int r = i >> 4, c4 = (i & 15) << 2;
            int l = q2_0 * NCS + r;
            float4 v = make_float4(0.f, 0.f, 0.f, 0.f);
            if (l < NL) v = *reinterpret_cast<const float4*>(q + (size_t)(b * NL + l) * ND + h * NDH + c4);
            float* d = &Dm[r * ASTR + c4];
            d[0] = v.x; d[1] = v.y; d[2] = v.z; d[3] = v.w;
        }
        for (int i = tid; i < 129 * 16; i += 256) {
            int r = i >> 4, c4 = (i & 15) << 2;
            float4 v = make_float4(0.f, 0.f, 0.f, 0.f);
            if (r < 128) v = *reinterpret_cast<const float4*>(posc + (size_t)r * ND + h * NDH + c4);
            float* d = &kb[r * ASTR + c4];
            d[0] = v.x; d[1] = v.y; d[2] = v.z; d[3] = v.w;
        }
        __syncthreads();

        int pcrow[4]; bool seg1[4];
        #pragma unroll
        for (int i = 0; i < 4; i++) {
            int c = lane + 32 * i;
            seg1[i] = (c >= cstar);
            pcrow[i] = seg1[i] ? (c - cstar) : (base0 + c);
        }
        ull acc[4][4];
        #pragma unroll
        for (int s = 0; s < 4; s++)
            #pragma unroll
            for (int i = 0; i < 4; i++) acc[s][i] = 0ull;
        for (int dp = 0; dp < 32; dp++) {
            ull q0[4], q1[4];
            #pragma unroll
            for (int s = 0; s < 4; s++) {
                q0[s] = *reinterpret_cast<const ull*>(&Dm[(s0 + s) * ASTR + 2 * dp]);
                q1[s] = *reinterpret_cast<const ull*>(&Dm[(32 + s0 + s) * ASTR + 2 * dp]);
            }
            #pragma unroll
            for (int i = 0; i < 4; i++) {
                ull pv = *reinterpret_cast<const ull*>(&kb[pcrow[i] * ASTR + 2 * dp]);
                ull p0 = seg1[i] ? 0ull : pv;
                ull p1 = seg1[i] ? pv : 0ull;
                #pragma unroll
                for (int s = 0; s < 4; s++) {
                    fma2(acc[s][i], q0[s], p0);
                    fma2(acc[s][i], q1[s], p1);
                }
            }
        }
        #pragma unroll
        for (int s = 0; s < 4; s++)
            #pragma unroll
            for (int i = 0; i < 4; i++) {
                int c = lane + 32 * i;
                float v = sc[(s0 + s) * 256 + c] + fold2(acc[s][i]);
                if (c >= 64 && (c - 64) >= qc) v = -1e30f;
                sc[(s0 + s) * 256 + c] = v;
            }
    }
    __syncthreads();

    // ---- Phase B: post scores -> sc[:,128:256]
    for (int i = tid; i < 128 * 16; i += 256) {
        int r = i >> 4, c4 = (i & 15) << 2;
        float4 v = *reinterpret_cast<const float4*>(post + (size_t)r * ND + h * NDH + c4);
        float* d = &kb[r * ASTR + c4];
        d[0] = v.x; d[1] = v.y; d[2] = v.z; d[3] = v.w;
    }
    __syncthreads();
    {
        ull acc[4][4];
        #pragma unroll
        for (int s = 0; s < 4; s++)
            #pragma unroll
            for (int i = 0; i < 4; i++) acc[s][i] = 0ull;
        for (int dp = 0; dp < 32; dp++) {
            ull rr = *reinterpret_cast<const ull*>(&rrbs[2 * dp]);
            ull qv[4];
            #pragma unroll
            for (int s = 0; s < 4; s++)
                qv[s] = add2(*reinterpret_cast<const ull*>(&qs[(s0 + s) * 64 + 2 * dp]), rr);
            #pragma unroll
            for (int i = 0; i < 4; i++) {
                ull kv = *reinterpret_cast<const ull*>(&kb[(lane + 32 * i) * ASTR + 2 * dp]);
                #pragma unroll
                for (int s = 0; s < 4; s++) fma2(acc[s][i], qv[s], kv);
            }
        }
        #pragma unroll
        for (int s = 0; s < 4; s++)
            #pragma unroll
            for (int i = 0; i < 4; i++)
                sc[(s0 + s) * 256 + 128 + lane + 32 * i] = fold2(acc[s][i]);
    }
    __syncthreads();

    // ---- Phase C: band scores
    for (int i = tid; i < 160 * 16; i += 256) {
        int r = i >> 4, c4 = (i & 15) << 2;
        int idx = l0 + 1 + r;
        float4 v = make_float4(0.f, 0.f, 0.f, 0.f);
        if (idx < NWINROWS)
            v = *reinterpret_cast<const float4*>(kwin + (size_t)(b * NWINROWS + idx) * ND + h * NDH + c4);
        float* d = &kb[r * ASTR + c4];
        d[0] = v.x; d[1] = v.y; d[2] = v.z; d[3] = v.w;
    }
    __syncthreads();
    {
        ull acc[4][5];
        #pragma unroll
        for (int s = 0; s < 4; s++)
            #pragma unroll
            for (int i = 0; i < 5; i++) acc[s][i] = 0ull;
        for (int dp = 0; dp < 32; dp++) {
            ull rw = *reinterpret_cast<const ull*>(&rwbs[2 * dp]);
            ull qv[4];
            #pragma unroll
            for (int s = 0; s < 4; s++)
                qv[s] = add2(*reinterpret_cast<const ull*>(&qs[(s0 + s) * 64 + 2 * dp]), rw);
            #pragma unroll
            for (int i = 0; i < 5; i++) {
                ull kv = *reinterpret_cast<const ull*>(&kb[(lane + 32 * i) * ASTR + 2 * dp]);
                #pragma unroll
                for (int s = 0; s < 4; s++) fma2(acc[s][i], qv[s], kv);
            }
        }
        #pragma unroll
        for (int s = 0; s < 4; s++)
            #pragma unroll
            for (int i = 0; i < 5; i++)
                Dm[(s0 + s) * 160 + lane + 32 * i] = fold2(acc[s][i]);
    }
    __syncthreads();
    for (int i = tid; i < 32 * 128; i += 256) {
        int qi = i >> 7, j = i & 127;
        sc[qi * 256 + 128 + j] += Dm[qi * 160 + qi + j];
    }
    __syncthreads();

    // ---- softmax
    {
        const int w = tid >> 5, ln = tid & 31;
        for (int r = w; r < 32; r += 8) {
            float m = -1e30f;
            for (int c = ln; c < 256; c += 32) m = fmaxf(m, sc[r * 256 + c]);
            #pragma unroll
            for (int o = 16; o; o >>= 1) m = fmaxf(m, __shfl_xor_sync(0xffffffffu, m, o));
            float s = 0.f;
            for (int c = ln; c < 256; c += 32) {
                float e = __expf(sc[r * 256 + c] - m);
                sc[r * 256 + c] = e;
                s += e;
            }
            #pragma unroll
            for (int o = 16; o; o >>= 1) s += __shfl_xor_sync(0xffffffffu, s, o);
            float inv = 1.f / s;
            for (int c = ln; c < 256; c += 32) sc[r * 256 + c] *= inv;
        }
    }
    __syncthreads();

    // ---- Phase D: AV
    ull av[4] = {0ull, 0ull, 0ull, 0ull};
    for (int i = tid; i < 128 * 16; i += 256) {
        int r = i >> 4, c4 = (i & 15) << 2;
        float4 v = *reinterpret_cast<const float4*>(vcomp + (size_t)(b * NNC + r) * ND + h * NDH + c4);
        float* d = &kb[r * ASTR + c4];
        d[0] = v.x; d[1] = v.y; d[2] = v.z; d[3] = v.w;
    }
    __syncthreads();
    for (int c = 0; c < NNC; c++) {
        ull vv = *reinterpret_cast<const ull*>(&kb[c * ASTR + 2 * lane]);
        #pragma unroll
        for (int s = 0; s < 4; s++) {
            float sv = sc[(s0 + s) * 256 + c];
            fma2(av[s], pack2(sv), vv);
        }
    }
    __syncthreads();
    for (int i = tid; i < 160 * 16; i += 256) {
        int r = i >> 4, c4 = (i & 15) << 2;
        int idx = l0 + 1 + r;
        float4 v = make_float4(0.f, 0.f, 0.f, 0.f);
        if (idx < NWINROWS)
            v = *reinterpret_cast<const float4*>(vwin + (size_t)(b * NWINROWS + idx) * ND + h * NDH + c4);
        float* d = &kb[r * ASTR + c4];
        d[0] = v.x; d[1] = v.y; d[2] = v.z; d[3] = v.w;
    }
    __syncthreads();
    for (int r = 0; r < 160; r++) {
        ull vv = *reinterpret_cast<const ull*>(&kb[r * ASTR + 2 * lane]);
        #pragma unroll
        for (int s = 0; s < 4; s++) {
            int j = r - (s0 + s);
            if ((unsigned)j < 128u) {
                float sv = sc[(s0 + s) * 256 + 128 + j];
                fma2(av[s], pack2(sv), vv);
            }
        }
    }
    #pragma unroll
    for (int s = 0; s < 4; s++) {
        float2 o = unpack2(av[s]);
        const size_t base = (size_t)(b * NL + l0 + s0 + s) * ND + h * NDH + 2 * lane;
        __nv_bfloat16 h0 = __float2bfloat16(o.x), h1 = __float2bfloat16(o.y);
        __nv_bfloat16 l0b = __float2bfloat16(o.x - __bfloat162float(h0));
        __nv_bfloat16 l1b = __float2bfloat16(o.y - __bfloat162float(h1));
        *reinterpret_cast<__nv_bfloat162*>(ohi + base) = __nv_bfloat162(h0, h1);
        *reinterpret_cast<__nv_bfloat162*>(olo + base) = __nv_bfloat162(l0b, l1b);
    }
}

// ---------------- host launch ----------------
#define GETSYM(p, s) do { void* _t = nullptr; cudaGetSymbolAddress(&_t, s); (p) = decltype(p)(_t); } while (0)

static inline void tgemm_s(cudaStream_t st,
                           const __nv_bfloat16* Ahi, const __nv_bfloat16* Alo,
                           const __nv_bfloat16* Bhi, const __nv_bfloat16* Blo,
                           const float* bias, float* C0, float* C1, float* C2,
                           int M, int N, int K)
{
    dim3 grid(N / 128, M / 128);
    tgemm_kernel<<<grid, 256, TG_SMEM_TOTAL, st>>>(Ahi, Alo, Bhi, Blo, bias, C0, C1, C2, M, N, K);
}

extern "C" void kernel_launch(void* const* d_in, const int* in_sizes, int n_in,
                              void* d_out, int out_size)
{
    const float* h      = (const float*)d_in[0];
    const float* hcache = (const float*)d_in[1];
    const float* key_pe = (const float*)d_in[2];
    const float* poswin = (const float*)d_in[3];
    const float* Wq  = (const float*)d_in[4];
    const float* Wk  = (const float*)d_in[5];
    const float* Wv  = (const float*)d_in[6];
    const float* Wo  = (const float*)d_in[7];
    const float* Wd  = (const float*)d_in[8];
    const float* bd  = (const float*)d_in[9];
    const float* Wr  = (const float*)d_in[10];
    const float* br  = (const float*)d_in[11];
    const float* Wrc = (const float*)d_in[12];
    const float* brc = (const float*)d_in[13];
    const float* rrb = (const float*)d_in[14];
    const float* rwb = (const float*)d_in[15];
    const float* g_dp = (const float*)d_in[16];
    const float* b_dp = (const float*)d_in[17];
    const float* g_w  = (const float*)d_in[18];
    const float* b_w  = (const float*)d_in[19];
    float* outp = (float*)d_out;

    float *q, *kbp, *vbp, *sh, *shc, *sch, *schc, *hcm;
    float *hcmk, *hcmv, *kcomp, *vcomp, *hwk, *hwv, *kwin, *vwin, *post, *posc;
    GETSYM(q, g_q); GETSYM(kbp, g_kbp); GETSYM(vbp, g_vbp);
    GETSYM(sh, g_sh); GETSYM(shc, g_shc); GETSYM(sch, g_sch); GETSYM(schc, g_schc);
    GETSYM(hcm, g_hcm);
    GETSYM(hcmk, g_hcmk); GETSYM(hcmv, g_hcmv);
    GETSYM(kcomp, g_kcomp); GETSYM(vcomp, g_vcomp);
    GETSYM(hwk, g_hwk); GETSYM(hwv, g_hwv);
    GETSYM(kwin, g_kwin); GETSYM(vwin, g_vwin);
    GETSYM(post, g_post); GETSYM(posc, g_posc);

    __nv_bfloat16 *ahi, *alo, *xhi, *xlo, *yhi, *ylo, *phi, *plo, *ehi, *elo;
    __nv_bfloat16 *wqkvh, *wqkvl, *woh, *wol, *wrh, *wrl, *wrch, *wrcl;
    GETSYM(ahi, g_ahi); GETSYM(alo, g_alo);
    GETSYM(xhi, g_xhi); GETSYM(xlo, g_xlo);
    GETSYM(yhi, g_yhi); GETSYM(ylo, g_ylo);
    GETSYM(phi, g_phi); GETSYM(plo, g_plo);
    GETSYM(ehi, g_ehi); GETSYM(elo, g_elo);
    GETSYM(wqkvh, g_wqkvh); GETSYM(wqkvl, g_wqkvl);
    GETSYM(woh, g_woh); GETSYM(wol, g_wol);
    GETSYM(wrh, g_wrh); GETSYM(wrl, g_wrl); GETSYM(wrch, g_wrch); GETSYM(wrcl, g_wrcl);

    const int ATTN_SMEM = ATT_SMEM_F * (int)sizeof(float);
    cudaFuncSetAttribute(attn_kernel, cudaFuncAttributeMaxDynamicSharedMemorySize, ATTN_SMEM);
    cudaFuncSetAttribute(tgemm_kernel, cudaFuncAttributeMaxDynamicSharedMemorySize, TG_SMEM_TOTAL);

    // one-time stream/event creation (host resources only; no device memory)
    static cudaStream_t s1 = nullptr, s2 = nullptr;
    static cudaEvent_t evRoot = nullptr, evWk = nullptr, evSch = nullptr,
                       evQKV = nullptr, ev1 = nullptr, ev2 = nullptr;
    if (!s1) {
        cudaStreamCreateWithFlags(&s1, cudaStreamNonBlocking);
        cudaStreamCreateWithFlags(&s2, cudaStreamNonBlocking);
        cudaEventCreateWithFlags(&evRoot, cudaEventDisableTiming);
        cudaEventCreateWithFlags(&evWk,   cudaEventDisableTiming);
        cudaEventCreateWithFlags(&evSch,  cudaEventDisableTiming);
        cudaEventCreateWithFlags(&evQKV,  cudaEventDisableTiming);
        cudaEventCreateWithFlags(&ev1,    cudaEventDisableTiming);
        cudaEventCreateWithFlags(&ev2,    cudaEventDisableTiming);
    }

    const int M = NB * NL;   // 8192
    const int WSZ = ND * ND;
    const cudaStream_t s0 = 0;
    dim3 wg(32, 32);

    // ---- fork side streams from the launch stream (record precedes all waits)
    cudaEventRecord(evRoot, s0);
    cudaStreamWaitEvent(s1, evRoot, 0);
    cudaStreamWaitEvent(s2, evRoot, 0);

    // ---- s1 (part 1): sch producer FIRST — record evSch as early as possible
    gemv16_kernel<<<M / 64, 256, 0, s1>>>(h, Wd, bd, sh);
    chunk_softmax_kernel<<<NB * NNQ, 512, 0, s1>>>(sh, sch, NL);
    cudaEventRecord(evSch, s1);

    // ---- s2 (part 1): independent splits + positional GEMMs
    wsplit_kernel<<<wg, 256, 0, s2>>>(Wr,  wrh,  wrl,  1.f);
    wsplit_kernel<<<wg, 256, 0, s2>>>(Wrc, wrch, wrcl, 1.f);
    split_kernel<<<NW, 256, 0, s2>>>(poswin, phi, plo, NW, 0, 0);
    split_kernel<<<NNC, 256, 0, s2>>>(key_pe, ehi, elo, NNC, 0, 0);
    tgemm_s(s2, phi, plo, wrh, wrl, br, post, nullptr, nullptr, NW, ND, ND);
    tgemm_s(s2, ehi, elo, wrch, wrcl, brc, posc, nullptr, nullptr, NNC, ND, ND);
    split_kernel<<<NB * NW, 256, 0, s2>>>(hcache, yhi, ylo, NW, NCACHE, NCACHE - NW);

    // ---- s1 (part 2): hcache scores + compress + split
    gemv16_kernel<<<M / 64, 256, 0, s1>>>(hcache, Wd, bd, shc);
    chunk_softmax_kernel<<<NB * NNQ, 512, 0, s1>>>(shc, schc, NCACHE);
    compress_kernel<<<NB * NNQ, 256, 0, s1>>>(hcache, schc, hcm, NCACHE);
    split_kernel<<<NB * NNQ, 256, 0, s1>>>(hcm, xhi, xlo, NB * NNQ, 0, 0);

    // ================= s0: main chain =================
    wsplit_kernel<<<wg, 256, 0, s0>>>(Wq,  wqkvh,           wqkvl,           0.125f);
    wsplit_kernel<<<wg, 256, 0, s0>>>(Wk,  wqkvh + WSZ,     wqkvl + WSZ,     1.f);
    wsplit_kernel<<<wg, 256, 0, s0>>>(Wv,  wqkvh + 2 * WSZ, wqkvl + 2 * WSZ, 1.f);
    cudaEventRecord(evWk, s0);                 // Wk/Wv splits ready
    wsplit_kernel<<<wg, 256, 0, s0>>>(Wo,  woh,  wol,  1.f);
    split_kernel<<<M, 256, 0, s0>>>(h, ahi, alo, M, 0, 0);

    // fused q/k/v projection of h (N=3072)
    tgemm_s(s0, ahi, alo, wqkvh, wqkvl, nullptr, q, kbp, vbp, M, 3 * ND, ND);
    cudaEventRecord(evQKV, s0);                // kbp/vbp ready (for s2 window LNs)

    // fused compress+LN of block K/V -> kcomp/vcomp rows 64+ (needs sch)
    cudaStreamWaitEvent(s0, evSch, 0);
    {
        dim3 cg(NB * NNQ, 2);
        compress_ln_kernel<<<cg, 256, 0, s0>>>(kbp, vbp, sch, kcomp, vcomp, g_dp, b_dp);
    }

    // ---- s1 (part 3): cache K/V GEMM (needs evWk) + dual LN
    cudaStreamWaitEvent(s1, evWk, 0);
    tgemm_s(s1, xhi, xlo, wqkvh + WSZ, wqkvl + WSZ, nullptr, hcmk, hcmv, nullptr,
            NB * NNQ, 2 * ND, ND);
    {
        dim3 lg(NB * NNQ, 2);
        ln2_kernel<<<lg, 256, 0, s1>>>(hcmk, hcmv, kcomp, vcomp, g_dp, b_dp, NNQ, NNC, 0);
    }
    cudaEventRecord(ev1, s1);

    // ---- s2 (part 2): window-cache K/V GEMM + ALL window LNs (dual launches)
    cudaStreamWaitEvent(s2, evWk, 0);
    tgemm_s(s2, yhi, ylo, wqkvh + WSZ, wqkvl + WSZ, nullptr, hwk, hwv, nullptr,
            NB * NW, 2 * ND, ND);
    {
        dim3 lg(NB * NW, 2);
        ln2_kernel<<<lg, 256, 0, s2>>>(hwk, hwv, kwin, vwin, g_w, b_w, NW, NWINROWS, 0);
    }
    cudaStreamWaitEvent(s2, evQKV, 0);
    {
        dim3 lg(M, 2);
        ln2_kernel<<<lg, 256, 0, s2>>>(kbp, vbp, kwin, vwin, g_w, b_w, NL, NWINROWS, NW);
    }
    cudaEventRecord(ev2, s2);

    // ---- join side streams before attention
    cudaStreamWaitEvent(s0, ev1, 0);
    cudaStreamWaitEvent(s0, ev2, 0);

    // fused attention (rel-shift positional computed in-kernel; bf16 hi/lo out)
    attn_kernel<<<NB * NH * NNQ, 256, ATTN_SMEM, s0>>>(q, kcomp, vcomp, kwin, vwin,
                                                       post, posc, rwb, rrb, ahi, alo);

    // output projection
    tgemm_s(s0, ahi, alo, woh, wol, nullptr, outp, nullptr, nullptr, M, ND, ND);
}